// round 2
// baseline (speedup 1.0000x reference)
#include <cuda_runtime.h>
#include <math.h>

#define Bsz 16
#define Msz 512
#define HIDs 768
#define NH 12
#define HD 64
#define BHsz (Bsz*NH)

// Scratch (allocation-free rule: __device__ globals)
__device__ float g_Q[(size_t)Bsz*Msz*HIDs];     // 25.2 MB
__device__ float g_s[BHsz*Msz];                 // pair scores s[b,h,i] = q_i.q_{i+1}/64
__device__ float g_nasup[BHsz*Msz];             // neibor_attn at (i, i+1)
__device__ float g_nasub[BHsz*Msz];             // neibor_attn at (i+1, i)
__device__ float g_S[BHsz*Msz];                 // prefix sums of log(nasup+1e-9)

// ---------------------------------------------------------------------------
// K1: Q = X @ Wq + bq   (8192x768 @ 768x768, fp32)
// Classic 128x128x8 tile, 256 threads, 8x8 per thread.
// ---------------------------------------------------------------------------
__global__ __launch_bounds__(256, 2) void k_gemm(const float* __restrict__ A,
                                                 const float* __restrict__ W,
                                                 const float* __restrict__ bias) {
    const int K = HIDs;
    __shared__ float As[8][128];
    __shared__ float Bs[8][128];
    int tid  = threadIdx.x;
    int bm   = blockIdx.y * 128;
    int bn   = blockIdx.x * 128;
    int arow = tid >> 1;
    int acol = (tid & 1) * 4;
    int brow = tid >> 5;
    int bcol = (tid & 31) * 4;
    int tr   = (tid >> 4) * 8;
    int tc   = (tid & 15) * 8;

    float acc[8][8];
#pragma unroll
    for (int m = 0; m < 8; m++)
#pragma unroll
        for (int n = 0; n < 8; n++) acc[m][n] = 0.f;

    for (int k0 = 0; k0 < K; k0 += 8) {
        float4 av = *(const float4*)(A + (size_t)(bm + arow) * K + k0 + acol);
        As[acol + 0][arow] = av.x;
        As[acol + 1][arow] = av.y;
        As[acol + 2][arow] = av.z;
        As[acol + 3][arow] = av.w;
        *(float4*)(&Bs[brow][bcol]) =
            *(const float4*)(W + (size_t)(k0 + brow) * HIDs + bn + bcol);
        __syncthreads();
#pragma unroll
        for (int kk = 0; kk < 8; kk++) {
            float a[8], bv[8];
            *(float4*)(a)      = *(float4*)(&As[kk][tr]);
            *(float4*)(a + 4)  = *(float4*)(&As[kk][tr + 4]);
            *(float4*)(bv)     = *(float4*)(&Bs[kk][tc]);
            *(float4*)(bv + 4) = *(float4*)(&Bs[kk][tc + 4]);
#pragma unroll
            for (int m = 0; m < 8; m++)
#pragma unroll
                for (int n = 0; n < 8; n++) acc[m][n] += a[m] * bv[n];
        }
        __syncthreads();
    }
#pragma unroll
    for (int m = 0; m < 8; m++) {
        float* crow = g_Q + (size_t)(bm + tr + m) * HIDs + bn + tc;
#pragma unroll
        for (int n = 0; n < 8; n++) crow[n] = acc[m][n] + bias[bn + tc + n];
    }
}

// ---------------------------------------------------------------------------
// K2: pair scores s[b,h,i] = (q[b,i,h*64:].q[b,i+1,h*64:]) / 64,  i in [0,511)
// One block per (i,b), 12 warps = 12 heads.
// ---------------------------------------------------------------------------
__global__ void k_dots() {
    int i = blockIdx.x;          // 0..510
    int b = blockIdx.y;
    int w = threadIdx.x >> 5;    // head
    int lane = threadIdx.x & 31;
    const float* qa = g_Q + ((size_t)b * Msz + i) * HIDs;
    const float* qb = qa + HIDs;
    int d0 = w * 64 + lane;
    float p = qa[d0] * qb[d0] + qa[d0 + 32] * qb[d0 + 32];
#pragma unroll
    for (int off = 16; off; off >>= 1) p += __shfl_xor_sync(0xffffffffu, p, off);
    if (lane == 0) g_s[(b * NH + w) * Msz + i] = p * (1.0f / 64.0f);
}

// ---------------------------------------------------------------------------
// K3: per (b,h): 2-way softmax -> band neibor values -> log -> prefix sum S.
// One block of 512 threads per (b,h). Scan in double for accuracy.
// ---------------------------------------------------------------------------
__global__ void k_band(const float* __restrict__ prior, const int* __restrict__ mask) {
    int bh = blockIdx.x;
    int b  = bh / NH;
    int i  = threadIdx.x;
    __shared__ float  sh_s[Msz];
    __shared__ float  sh_an[Msz];
    __shared__ float  sh_ap[Msz];
    __shared__ double sh_sc[Msz];

    sh_s[i] = (i < Msz - 1) ? g_s[bh * Msz + i] : 0.f;
    __syncthreads();

    bool hp = (i > 0)       && (mask[b * Msz + i - 1] > 0);
    bool hn = (i < Msz - 1) && (mask[b * Msz + i + 1] > 0);
    float an = 0.f, ap = 0.f;
    if (hn && hp) {
        float sn = sh_s[i], sp = sh_s[i - 1];
        float m  = fmaxf(sn, sp);
        float en = expf(sn - m), ep = expf(sp - m);
        float z  = en + ep;
        an = en / z;
        ap = ep / z;
    } else if (hn) { an = 1.f; }
    else if (hp)   { ap = 1.f; }
    sh_an[i] = an;
    sh_ap[i] = ap;
    __syncthreads();

    float l = 0.f;
    if (i < Msz - 1) {
        float v    = sqrtf(sh_an[i] * sh_ap[i + 1] + 1e-4f);
        float prs  = prior[((size_t)b * Msz + i) * Msz + (i + 1)];
        float prb  = prior[((size_t)b * Msz + i + 1) * Msz + i];
        float nsup = prs + (1.f - prs) * v;
        float nsub = prb + (1.f - prb) * v;
        g_nasup[bh * Msz + i] = nsup;
        g_nasub[bh * Msz + i] = nsub;
        l = logf(nsup + 1e-9f);
    }
    sh_sc[i] = (double)l;
    __syncthreads();
    // Hillis-Steele inclusive scan
    for (int off = 1; off < Msz; off <<= 1) {
        double t = (i >= off) ? sh_sc[i - off] : 0.0;
        __syncthreads();
        sh_sc[i] += t;
        __syncthreads();
    }
    g_S[bh * Msz + i] = (i == 0) ? 0.f : (float)sh_sc[i - 1];
}

// ---------------------------------------------------------------------------
// K4: write both outputs.
//   neibor[b,h,i,k] = band ? precomputed : prior + (1-prior)*sqrt(eps)
//   g[b,h,i,k]      = (i==k) ? neibor_diag : exp(S[max]-S[min]) + 1e-4
// Block = 256 threads -> 4 rows, 8 cols/thread (two float4). Grid (128, H, B).
// ---------------------------------------------------------------------------
__global__ void k_out(const float* __restrict__ prior,
                      float* __restrict__ gout, float* __restrict__ nbout) {
    int b  = blockIdx.z, h = blockIdx.y;
    int bh = b * NH + h;
    __shared__ float shS[Msz], shsup[Msz], shsub[Msz];
    for (int j = threadIdx.x; j < Msz; j += 256) {
        shS[j]   = g_S[bh * Msz + j];
        shsup[j] = g_nasup[bh * Msz + j];
        shsub[j] = g_nasub[bh * Msz + j];
    }
    __syncthreads();

    int r  = threadIdx.x >> 6;                 // 0..3
    int i  = blockIdx.x * 4 + r;
    int c0 = (threadIdx.x & 63) * 8;
    float Si = shS[i];
    const float* prow = prior + ((size_t)b * Msz + i) * Msz;
    size_t obase = ((size_t)bh * Msz + i) * Msz;
    const float SQEPS = sqrtf(1e-4f);

#pragma unroll
    for (int v = 0; v < 2; v++) {
        int k0 = c0 + v * 4;
        float4 pr = *(const float4*)(prow + k0);
        float prv[4] = {pr.x, pr.y, pr.z, pr.w};
        float go[4], no[4];
#pragma unroll
        for (int j = 0; j < 4; j++) {
            int k   = k0 + j;
            float p = prv[j];
            float nb;
            if (k == i + 1)      nb = shsup[i];
            else if (k == i - 1) nb = shsub[k];
            else                 nb = p + (1.f - p) * SQEPS;
            float g;
            if (k == i) g = nb;
            else {
                float dS = (k > i) ? (shS[k] - Si) : (Si - shS[k]);
                float e  = (dS > -18.f) ? __expf(dS) : 0.f;
                g = e + 1e-4f;
            }
            go[j] = g;
            no[j] = nb;
        }
        *(float4*)(gout + obase + k0)  = make_float4(go[0], go[1], go[2], go[3]);
        *(float4*)(nbout + obase + k0) = make_float4(no[0], no[1], no[2], no[3]);
    }
}

extern "C" void kernel_launch(void* const* d_in, const int* in_sizes, int n_in,
                              void* d_out, int out_size) {
    const float* X     = (const float*)d_in[0];  // (16,512,768)
    const float* prior = (const float*)d_in[1];  // (16,1,512,512)
    const float* Wq    = (const float*)d_in[2];  // (768,768)
    const float* bq    = (const float*)d_in[3];  // (768,)
    const int*   mask  = (const int*)d_in[4];    // (16,512)
    float* out   = (float*)d_out;
    float* gout  = out;                                  // g_attn first
    float* nbout = out + (size_t)BHsz * Msz * Msz;       // then neibor_attn

    k_gemm<<<dim3(HIDs / 128, (Bsz * Msz) / 128), 256>>>(X, Wq, bq);
    k_dots<<<dim3(Msz - 1, Bsz), NH * 32>>>();
    k_band<<<BHsz, Msz>>>(prior, mask);
    k_out<<<dim3(Msz / 4, NH, Bsz), 256>>>(prior, gout, nbout);
}

// round 5
// speedup vs baseline: 1.6128x; 1.6128x over previous
#include <cuda_runtime.h>
#include <cuda_bf16.h>
#include <cstdint>
#include <cstddef>
#include <math.h>

#define Bsz 16
#define Msz 512
#define HIDs 768
#define NH 12
#define HD 64
#define BHsz (Bsz*NH)

#define BM 128
#define BN 128
#define BK 16
#define ASTR 24     // A smem row stride (bf16 elems)
#define BSTR 136    // B smem row stride
#define NIT (HIDs/BK)

// Scratch (__device__ globals; no allocation allowed)
__device__ float g_Q[(size_t)Bsz*Msz*HIDs];
__device__ __nv_bfloat16 g_Ah[(size_t)Bsz*Msz*HIDs];
__device__ __nv_bfloat16 g_Al[(size_t)Bsz*Msz*HIDs];
__device__ __nv_bfloat16 g_Wh[HIDs*HIDs];
__device__ __nv_bfloat16 g_Wl[HIDs*HIDs];
__device__ float g_s[BHsz*Msz];
__device__ float g_nasup[BHsz*Msz];
__device__ float g_nasub[BHsz*Msz];
__device__ float g_S[BHsz*Msz];

// ---------------------------------------------------------------------------
// Split fp32 -> bf16 hi + bf16 lo
// ---------------------------------------------------------------------------
__global__ void k_cvt(const float* __restrict__ x, __nv_bfloat16* __restrict__ hi,
                      __nv_bfloat16* __restrict__ lo, int n) {
    int idx = (blockIdx.x * blockDim.x + threadIdx.x) * 4;
    if (idx >= n) return;
    float4 v = *(const float4*)(x + idx);
    __nv_bfloat16 h0 = __float2bfloat16(v.x), h1 = __float2bfloat16(v.y);
    __nv_bfloat16 h2 = __float2bfloat16(v.z), h3 = __float2bfloat16(v.w);
    __nv_bfloat16 l0 = __float2bfloat16(v.x - __bfloat162float(h0));
    __nv_bfloat16 l1 = __float2bfloat16(v.y - __bfloat162float(h1));
    __nv_bfloat16 l2 = __float2bfloat16(v.z - __bfloat162float(h2));
    __nv_bfloat16 l3 = __float2bfloat16(v.w - __bfloat162float(h3));
    __nv_bfloat162 hp0, hp1, lp0, lp1;
    hp0.x = h0; hp0.y = h1; hp1.x = h2; hp1.y = h3;
    lp0.x = l0; lp0.y = l1; lp1.x = l2; lp1.y = l3;
    *(__nv_bfloat162*)(hi + idx)     = hp0;
    *(__nv_bfloat162*)(hi + idx + 2) = hp1;
    *(__nv_bfloat162*)(lo + idx)     = lp0;
    *(__nv_bfloat162*)(lo + idx + 2) = lp1;
}

// ---------------------------------------------------------------------------
// Helpers
// ---------------------------------------------------------------------------
__device__ __forceinline__ void cp16(void* s, const void* g) {
    unsigned sa = (unsigned)__cvta_generic_to_shared(s);
    asm volatile("cp.async.ca.shared.global [%0], [%1], 16;\n" :: "r"(sa), "l"(g));
}
__device__ __forceinline__ void ldm_x4(unsigned* r, unsigned a) {
    asm volatile("ldmatrix.sync.aligned.m8n8.x4.shared.b16 {%0,%1,%2,%3}, [%4];"
                 : "=r"(r[0]), "=r"(r[1]), "=r"(r[2]), "=r"(r[3]) : "r"(a));
}
__device__ __forceinline__ void ldm_x4_t(unsigned* r, unsigned a) {
    asm volatile("ldmatrix.sync.aligned.m8n8.x4.trans.shared.b16 {%0,%1,%2,%3}, [%4];"
                 : "=r"(r[0]), "=r"(r[1]), "=r"(r[2]), "=r"(r[3]) : "r"(a));
}
__device__ __forceinline__ void mma16816(float* c, const unsigned* a, const unsigned* b) {
    asm volatile(
        "mma.sync.aligned.m16n8k16.row.col.f32.bf16.bf16.f32 "
        "{%0,%1,%2,%3}, {%4,%5,%6,%7}, {%8,%9}, {%0,%1,%2,%3};"
        : "+f"(c[0]), "+f"(c[1]), "+f"(c[2]), "+f"(c[3])
        : "r"(a[0]), "r"(a[1]), "r"(a[2]), "r"(a[3]), "r"(b[0]), "r"(b[1]));
}
__device__ __forceinline__ void stcs4(float* p, float a, float b, float c, float d) {
    asm volatile("st.global.cs.v4.f32 [%0], {%1,%2,%3,%4};"
                 :: "l"(p), "f"(a), "f"(b), "f"(c), "f"(d) : "memory");
}

// ---------------------------------------------------------------------------
// K1: Q = X @ Wq + bq via bf16-split tensor cores.
// C = Ah*Bh + Ah*Bl + Al*Bh, fp32 accumulate.
// ---------------------------------------------------------------------------
__global__ __launch_bounds__(256) void k_gemm_mma(const float* __restrict__ bias) {
    __shared__ __align__(16) __nv_bfloat16 sAh[2][BM * ASTR];
    __shared__ __align__(16) __nv_bfloat16 sAl[2][BM * ASTR];
    __shared__ __align__(16) __nv_bfloat16 sBh[2][BK * BSTR];
    __shared__ __align__(16) __nv_bfloat16 sBl[2][BK * BSTR];

    int tid  = threadIdx.x;
    int bm   = blockIdx.y * BM;
    int bn   = blockIdx.x * BN;
    int warp = tid >> 5, lane = tid & 31;
    int wm = (warp & 3) * 32;
    int wn = (warp >> 2) * 64;

    int arow = tid >> 1, acol = (tid & 1) * 8;
    int brow = tid >> 4, bcol = (tid & 15) * 8;

    float acc[2][8][4];
#pragma unroll
    for (int m = 0; m < 2; m++)
#pragma unroll
        for (int n = 0; n < 8; n++)
#pragma unroll
            for (int j = 0; j < 4; j++) acc[m][n][j] = 0.f;

    // prologue: stage 0
    cp16(&sAh[0][arow * ASTR + acol], g_Ah + (size_t)(bm + arow) * HIDs + acol);
    cp16(&sAl[0][arow * ASTR + acol], g_Al + (size_t)(bm + arow) * HIDs + acol);
    cp16(&sBh[0][brow * BSTR + bcol], g_Wh + (size_t)brow * HIDs + bn + bcol);
    cp16(&sBl[0][brow * BSTR + bcol], g_Wl + (size_t)brow * HIDs + bn + bcol);
    asm volatile("cp.async.commit_group;");

    for (int it = 0; it < NIT; it++) {
        int buf = it & 1;
        if (it + 1 < NIT) {
            int k0 = (it + 1) * BK, nb = buf ^ 1;
            cp16(&sAh[nb][arow * ASTR + acol], g_Ah + (size_t)(bm + arow) * HIDs + k0 + acol);
            cp16(&sAl[nb][arow * ASTR + acol], g_Al + (size_t)(bm + arow) * HIDs + k0 + acol);
            cp16(&sBh[nb][brow * BSTR + bcol], g_Wh + (size_t)(k0 + brow) * HIDs + bn + bcol);
            cp16(&sBl[nb][brow * BSTR + bcol], g_Wl + (size_t)(k0 + brow) * HIDs + bn + bcol);
            asm volatile("cp.async.commit_group;");
            asm volatile("cp.async.wait_group 1;");
        } else {
            asm volatile("cp.async.wait_group 0;");
        }
        __syncthreads();

        unsigned afh[2][4], afl[2][4];
        unsigned aBaseH = (unsigned)__cvta_generic_to_shared(&sAh[buf][0]);
        unsigned aBaseL = (unsigned)__cvta_generic_to_shared(&sAl[buf][0]);
#pragma unroll
        for (int mt = 0; mt < 2; mt++) {
            unsigned off = ((wm + mt * 16 + (lane & 15)) * ASTR + (lane >> 4) * 8) * 2;
            ldm_x4(afh[mt], aBaseH + off);
            ldm_x4(afl[mt], aBaseL + off);
        }
        unsigned bfh[4][4], bfl[4][4];
        unsigned bBaseH = (unsigned)__cvta_generic_to_shared(&sBh[buf][0]);
        unsigned bBaseL = (unsigned)__cvta_generic_to_shared(&sBl[buf][0]);
#pragma unroll
        for (int nt = 0; nt < 4; nt++) {
            unsigned off = ((lane & 15) * BSTR + wn + nt * 16 + (lane >> 4) * 8) * 2;
            ldm_x4_t(bfh[nt], bBaseH + off);
            ldm_x4_t(bfl[nt], bBaseL + off);
        }
#pragma unroll
        for (int mt = 0; mt < 2; mt++)
#pragma unroll
            for (int nt = 0; nt < 4; nt++) {
                mma16816(acc[mt][2 * nt],     afh[mt], &bfh[nt][0]);
                mma16816(acc[mt][2 * nt + 1], afh[mt], &bfh[nt][2]);
                mma16816(acc[mt][2 * nt],     afh[mt], &bfl[nt][0]);
                mma16816(acc[mt][2 * nt + 1], afh[mt], &bfl[nt][2]);
                mma16816(acc[mt][2 * nt],     afl[mt], &bfh[nt][0]);
                mma16816(acc[mt][2 * nt + 1], afl[mt], &bfh[nt][2]);
            }
        __syncthreads();
    }

    // epilogue: + bias, write fp32 Q
#pragma unroll
    for (int mt = 0; mt < 2; mt++) {
        int row0 = bm + wm + mt * 16 + (lane >> 2);
#pragma unroll
        for (int n8 = 0; n8 < 8; n8++) {
            int col = bn + wn + n8 * 8 + (lane & 3) * 2;
            float b0 = bias[col], b1 = bias[col + 1];
            float2 v0, v1;
            v0.x = acc[mt][n8][0] + b0; v0.y = acc[mt][n8][1] + b1;
            v1.x = acc[mt][n8][2] + b0; v1.y = acc[mt][n8][3] + b1;
            *(float2*)(g_Q + (size_t)row0 * HIDs + col)       = v0;
            *(float2*)(g_Q + (size_t)(row0 + 8) * HIDs + col) = v1;
        }
    }
}

// ---------------------------------------------------------------------------
// K2: pair scores s[b,h,i] = (q_i . q_{i+1}) / 64
// ---------------------------------------------------------------------------
__global__ void k_dots() {
    int i = blockIdx.x;
    int b = blockIdx.y;
    int w = threadIdx.x >> 5;
    int lane = threadIdx.x & 31;
    const float* qa = g_Q + ((size_t)b * Msz + i) * HIDs;
    const float* qb = qa + HIDs;
    int d0 = w * 64 + lane;
    float p = qa[d0] * qb[d0] + qa[d0 + 32] * qb[d0 + 32];
#pragma unroll
    for (int off = 16; off; off >>= 1) p += __shfl_xor_sync(0xffffffffu, p, off);
    if (lane == 0) g_s[(b * NH + w) * Msz + i] = p * (1.0f / 64.0f);
}

// ---------------------------------------------------------------------------
// K3: softmax band + prefix sums
// ---------------------------------------------------------------------------
__global__ void k_band(const float* __restrict__ prior, const int* __restrict__ mask) {
    int bh = blockIdx.x;
    int b  = bh / NH;
    int i  = threadIdx.x;
    __shared__ float  sh_s[Msz];
    __shared__ float  sh_an[Msz];
    __shared__ float  sh_ap[Msz];
    __shared__ double sh_sc[Msz];

    sh_s[i] = (i < Msz - 1) ? g_s[bh * Msz + i] : 0.f;
    __syncthreads();

    bool hp = (i > 0)       && (mask[b * Msz + i - 1] > 0);
    bool hn = (i < Msz - 1) && (mask[b * Msz + i + 1] > 0);
    float an = 0.f, ap = 0.f;
    if (hn && hp) {
        float sn = sh_s[i], sp = sh_s[i - 1];
        float m  = fmaxf(sn, sp);
        float en = expf(sn - m), ep = expf(sp - m);
        float z  = en + ep;
        an = en / z;
        ap = ep / z;
    } else if (hn) { an = 1.f; }
    else if (hp)   { ap = 1.f; }
    sh_an[i] = an;
    sh_ap[i] = ap;
    __syncthreads();

    float l = 0.f;
    if (i < Msz - 1) {
        float v    = sqrtf(sh_an[i] * sh_ap[i + 1] + 1e-4f);
        float prs  = prior[((size_t)b * Msz + i) * Msz + (i + 1)];
        float prb  = prior[((size_t)b * Msz + i + 1) * Msz + i];
        float nsup = prs + (1.f - prs) * v;
        float nsub = prb + (1.f - prb) * v;
        g_nasup[bh * Msz + i] = nsup;
        g_nasub[bh * Msz + i] = nsub;
        l = logf(nsup + 1e-9f);
    }
    sh_sc[i] = (double)l;
    __syncthreads();
    for (int off = 1; off < Msz; off <<= 1) {
        double t = (i >= off) ? sh_sc[i - off] : 0.0;
        __syncthreads();
        sh_sc[i] += t;
        __syncthreads();
    }
    g_S[bh * Msz + i] = (i == 0) ? 0.f : (float)sh_sc[i - 1];
}

// ---------------------------------------------------------------------------
// K4: output writer. Grid (Msz/4, Bsz); h-loop inside: prior read once,
// streamed stores. S for all 12 heads staged in smem.
// ---------------------------------------------------------------------------
__global__ __launch_bounds__(256) void k_out(const float* __restrict__ prior,
                                             float* __restrict__ gout,
                                             float* __restrict__ nbout) {
    int b = blockIdx.y;
    __shared__ float shS[NH][Msz];  // 24 KB
    const float* Sbase = g_S + (size_t)b * NH * Msz;
    for (int idx = threadIdx.x * 4; idx < NH * Msz; idx += 256 * 4)
        *(float4*)(&shS[0][0] + idx) = *(const float4*)(Sbase + idx);
    __syncthreads();

    int r  = threadIdx.x >> 6;
    int i  = blockIdx.x * 4 + r;
    int c0 = (threadIdx.x & 63) * 8;
    const float SQEPS = 0.01f;  // sqrt(1e-4)

    const float* prow = prior + ((size_t)b * Msz + i) * Msz + c0;
    float4 p0 = *(const float4*)prow;
    float4 p1 = *(const float4*)(prow + 4);
    float pv[8];
    pv[0] = p0.x; pv[1] = p0.y; pv[2] = p0.z; pv[3] = p0.w;
    pv[4] = p1.x; pv[5] = p1.y; pv[6] = p1.z; pv[7] = p1.w;
    float nbg[8];
#pragma unroll
    for (int j = 0; j < 8; j++) nbg[j] = pv[j] + (1.f - pv[j]) * SQEPS;

    bool hasdiag = (i >= c0) && (i < c0 + 8);
    bool hasup   = (i + 1 >= c0) && (i + 1 < c0 + 8) && (i + 1 < Msz);
    bool hassub  = (i - 1 >= c0) && (i - 1 < c0 + 8) && (i >= 1);

    for (int h = 0; h < NH; h++) {
        int bh   = b * NH + h;
        float Si = shS[h][i];
        float sv[8];
        *(float4*)(sv)     = *(float4*)&shS[h][c0];
        *(float4*)(sv + 4) = *(float4*)&shS[h][c0 + 4];

        float go[8], no[8];
#pragma unroll
        for (int j = 0; j < 8; j++) {
            int k    = c0 + j;
            float dS = (k > i) ? (sv[j] - Si) : (Si - sv[j]);
            float e  = (dS > -18.f) ? __expf(dS) : 0.f;
            go[j] = e + 1e-4f;
            no[j] = nbg[j];
        }
        if (hasdiag) go[i - c0] = nbg[i - c0];
        if (hasup)   no[i + 1 - c0] = g_nasup[bh * Msz + i];
        if (hassub)  no[i - 1 - c0] = g_nasub[bh * Msz + (i - 1)];

        size_t off = ((size_t)bh * Msz + i) * Msz + c0;
        stcs4(gout + off,      go[0], go[1], go[2], go[3]);
        stcs4(gout + off + 4,  go[4], go[5], go[6], go[7]);
        stcs4(nbout + off,     no[0], no[1], no[2], no[3]);
        stcs4(nbout + off + 4, no[4], no[5], no[6], no[7]);
    }
}

extern "C" void kernel_launch(void* const* d_in, const int* in_sizes, int n_in,
                              void* d_out, int out_size) {
    const float* X     = (const float*)d_in[0];  // (16,512,768)
    const float* prior = (const float*)d_in[1];  // (16,1,512,512)
    const float* Wq    = (const float*)d_in[2];  // (768,768)
    const float* bq    = (const float*)d_in[3];  // (768,)
    const int*   mask  = (const int*)d_in[4];    // (16,512)
    float* out   = (float*)d_out;
    float* gout  = out;
    float* nbout = out + (size_t)BHsz * Msz * Msz;

    __nv_bfloat16 *dAh, *dAl, *dWh, *dWl;
    cudaGetSymbolAddress((void**)&dAh, g_Ah);
    cudaGetSymbolAddress((void**)&dAl, g_Al);
    cudaGetSymbolAddress((void**)&dWh, g_Wh);
    cudaGetSymbolAddress((void**)&dWl, g_Wl);

    int nX = Bsz * Msz * HIDs;
    int nW = HIDs * HIDs;
    k_cvt<<<(nX / 4 + 255) / 256, 256>>>(X, dAh, dAl, nX);
    k_cvt<<<(nW / 4 + 255) / 256, 256>>>(Wq, dWh, dWl, nW);
    k_gemm_mma<<<dim3(HIDs / BN, (Bsz * Msz) / BM), 256>>>(bq);
    k_dots<<<dim3(Msz - 1, Bsz), NH * 32>>>();
    k_band<<<BHsz, Msz>>>(prior, mask);
    k_out<<<dim3(Msz / 4, Bsz), 256>>>(prior, gout, nbout);
}

// round 8
// speedup vs baseline: 2.1728x; 1.3472x over previous
#include <cuda_runtime.h>
#include <cuda_bf16.h>
#include <cstdint>
#include <cstddef>
#include <math.h>

#define Bsz 16
#define Msz 512
#define HIDs 768
#define NH 12
#define HD 64
#define BHsz (Bsz*NH)

#define BM 128
#define BN 128
#define BK 32
#define ASTR 40     // A smem row stride (bf16): 80B -> 20-bank skew, conflict-free
#define BSTR 136    // B smem row stride: 272B -> 4-bank skew, conflict-free
#define NIT (HIDs/BK)
// dynamic smem layout (bf16 elems)
#define A_STAGE (BM*ASTR)          // 5120
#define B_STAGE (BK*BSTR)          // 4352
#define OFF_AH 0
#define OFF_AL (2*A_STAGE)         // 10240
#define OFF_BH (4*A_STAGE)         // 20480
#define OFF_BL (4*A_STAGE + 2*B_STAGE)
#define SMEM_BYTES ((4*A_STAGE + 4*B_STAGE) * 2)

// Scratch (__device__ globals; no allocation allowed)
__device__ float g_Q[(size_t)Bsz*Msz*HIDs];
__device__ __nv_bfloat16 g_Ah[(size_t)Bsz*Msz*HIDs];
__device__ __nv_bfloat16 g_Al[(size_t)Bsz*Msz*HIDs];
__device__ __nv_bfloat16 g_Wh[HIDs*HIDs];
__device__ __nv_bfloat16 g_Wl[HIDs*HIDs];
__device__ float g_s[BHsz*Msz];
__device__ float g_nasup[BHsz*Msz];
__device__ float g_nasub[BHsz*Msz];
__device__ float g_S[BHsz*Msz];

// ---------------------------------------------------------------------------
// Split fp32 -> bf16 hi + bf16 lo
// ---------------------------------------------------------------------------
__global__ void k_cvt(const float* __restrict__ x, __nv_bfloat16* __restrict__ hi,
                      __nv_bfloat16* __restrict__ lo, int n) {
    int idx = (blockIdx.x * blockDim.x + threadIdx.x) * 4;
    if (idx >= n) return;
    float4 v = *(const float4*)(x + idx);
    __nv_bfloat16 h0 = __float2bfloat16(v.x), h1 = __float2bfloat16(v.y);
    __nv_bfloat16 h2 = __float2bfloat16(v.z), h3 = __float2bfloat16(v.w);
    __nv_bfloat16 l0 = __float2bfloat16(v.x - __bfloat162float(h0));
    __nv_bfloat16 l1 = __float2bfloat16(v.y - __bfloat162float(h1));
    __nv_bfloat16 l2 = __float2bfloat16(v.z - __bfloat162float(h2));
    __nv_bfloat16 l3 = __float2bfloat16(v.w - __bfloat162float(h3));
    __nv_bfloat162 hp0, hp1, lp0, lp1;
    hp0.x = h0; hp0.y = h1; hp1.x = h2; hp1.y = h3;
    lp0.x = l0; lp0.y = l1; lp1.x = l2; lp1.y = l3;
    *(__nv_bfloat162*)(hi + idx)     = hp0;
    *(__nv_bfloat162*)(hi + idx + 2) = hp1;
    *(__nv_bfloat162*)(lo + idx)     = lp0;
    *(__nv_bfloat162*)(lo + idx + 2) = lp1;
}

// ---------------------------------------------------------------------------
// Helpers
// ---------------------------------------------------------------------------
__device__ __forceinline__ void cp16(__nv_bfloat16* s, const __nv_bfloat16* g) {
    unsigned sa = (unsigned)__cvta_generic_to_shared(s);
    asm volatile("cp.async.ca.shared.global [%0], [%1], 16;\n" :: "r"(sa), "l"(g));
}
__device__ __forceinline__ void ldm_x4(unsigned* r, unsigned a) {
    asm volatile("ldmatrix.sync.aligned.m8n8.x4.shared.b16 {%0,%1,%2,%3}, [%4];"
                 : "=r"(r[0]), "=r"(r[1]), "=r"(r[2]), "=r"(r[3]) : "r"(a));
}
__device__ __forceinline__ void ldm_x4_t(unsigned* r, unsigned a) {
    asm volatile("ldmatrix.sync.aligned.m8n8.x4.trans.shared.b16 {%0,%1,%2,%3}, [%4];"
                 : "=r"(r[0]), "=r"(r[1]), "=r"(r[2]), "=r"(r[3]) : "r"(a));
}
__device__ __forceinline__ void mma16816(float* c, const unsigned* a, const unsigned* b) {
    asm volatile(
        "mma.sync.aligned.m16n8k16.row.col.f32.bf16.bf16.f32 "
        "{%0,%1,%2,%3}, {%4,%5,%6,%7}, {%8,%9}, {%0,%1,%2,%3};"
        : "+f"(c[0]), "+f"(c[1]), "+f"(c[2]), "+f"(c[3])
        : "r"(a[0]), "r"(a[1]), "r"(a[2]), "r"(a[3]), "r"(b[0]), "r"(b[1]));
}
__device__ __forceinline__ void stcs4(float* p, float a, float b, float c, float d) {
    asm volatile("st.global.cs.v4.f32 [%0], {%1,%2,%3,%4};"
                 :: "l"(p), "f"(a), "f"(b), "f"(c), "f"(d) : "memory");
}

// ---------------------------------------------------------------------------
// K1: Q = X @ Wq + bq via bf16-split tensor cores (Ah*Bh + Ah*Bl + Al*Bh).
// BK=32, 2-stage cp.async, dynamic smem.
// ---------------------------------------------------------------------------
__global__ __launch_bounds__(256) void k_gemm_mma(const float* __restrict__ bias) {
    extern __shared__ __align__(16) __nv_bfloat16 smem[];
    __nv_bfloat16* sAh = smem + OFF_AH;
    __nv_bfloat16* sAl = smem + OFF_AL;
    __nv_bfloat16* sBh = smem + OFF_BH;
    __nv_bfloat16* sBl = smem + OFF_BL;

    int tid  = threadIdx.x;
    int bm   = blockIdx.y * BM;
    int bn   = blockIdx.x * BN;
    int warp = tid >> 5, lane = tid & 31;
    int wm = (warp & 3) * 32;
    int wn = (warp >> 2) * 64;

    int arow = tid >> 1, acol = (tid & 1) * 16;   // elems
    int brow = tid >> 3, bcol = (tid & 7) * 16;   // elems

    float acc[2][8][4];
#pragma unroll
    for (int m = 0; m < 2; m++)
#pragma unroll
        for (int n = 0; n < 8; n++)
#pragma unroll
            for (int j = 0; j < 4; j++) acc[m][n][j] = 0.f;

    // prologue: stage 0, k0 = 0
    {
        const __nv_bfloat16* gah = g_Ah + (size_t)(bm + arow) * HIDs + acol;
        const __nv_bfloat16* gal = g_Al + (size_t)(bm + arow) * HIDs + acol;
        const __nv_bfloat16* gbh = g_Wh + (size_t)brow * HIDs + bn + bcol;
        const __nv_bfloat16* gbl = g_Wl + (size_t)brow * HIDs + bn + bcol;
        __nv_bfloat16* dah = sAh + arow * ASTR + acol;
        __nv_bfloat16* dal = sAl + arow * ASTR + acol;
        __nv_bfloat16* dbh = sBh + brow * BSTR + bcol;
        __nv_bfloat16* dbl = sBl + brow * BSTR + bcol;
        cp16(dah, gah); cp16(dah + 8, gah + 8);
        cp16(dal, gal); cp16(dal + 8, gal + 8);
        cp16(dbh, gbh); cp16(dbh + 8, gbh + 8);
        cp16(dbl, gbl); cp16(dbl + 8, gbl + 8);
        asm volatile("cp.async.commit_group;");
    }

    for (int it = 0; it < NIT; it++) {
        int s = it & 1;
        if (it + 1 < NIT) {
            int k0 = (it + 1) * BK, ns = s ^ 1;
            const __nv_bfloat16* gah = g_Ah + (size_t)(bm + arow) * HIDs + k0 + acol;
            const __nv_bfloat16* gal = g_Al + (size_t)(bm + arow) * HIDs + k0 + acol;
            const __nv_bfloat16* gbh = g_Wh + (size_t)(k0 + brow) * HIDs + bn + bcol;
            const __nv_bfloat16* gbl = g_Wl + (size_t)(k0 + brow) * HIDs + bn + bcol;
            __nv_bfloat16* dah = sAh + ns * A_STAGE + arow * ASTR + acol;
            __nv_bfloat16* dal = sAl + ns * A_STAGE + arow * ASTR + acol;
            __nv_bfloat16* dbh = sBh + ns * B_STAGE + brow * BSTR + bcol;
            __nv_bfloat16* dbl = sBl + ns * B_STAGE + brow * BSTR + bcol;
            cp16(dah, gah); cp16(dah + 8, gah + 8);
            cp16(dal, gal); cp16(dal + 8, gal + 8);
            cp16(dbh, gbh); cp16(dbh + 8, gbh + 8);
            cp16(dbl, gbl); cp16(dbl + 8, gbl + 8);
            asm volatile("cp.async.commit_group;");
            asm volatile("cp.async.wait_group 1;");
        } else {
            asm volatile("cp.async.wait_group 0;");
        }
        __syncthreads();

        unsigned aBaseH = (unsigned)__cvta_generic_to_shared(sAh + s * A_STAGE);
        unsigned aBaseL = (unsigned)__cvta_generic_to_shared(sAl + s * A_STAGE);
        unsigned bBaseH = (unsigned)__cvta_generic_to_shared(sBh + s * B_STAGE);
        unsigned bBaseL = (unsigned)__cvta_generic_to_shared(sBl + s * B_STAGE);

#pragma unroll
        for (int kk = 0; kk < BK; kk += 16) {
            unsigned afh[2][4], afl[2][4];
#pragma unroll
            for (int mt = 0; mt < 2; mt++) {
                unsigned off = ((wm + mt * 16 + (lane & 15)) * ASTR + kk + (lane >> 4) * 8) * 2;
                ldm_x4(afh[mt], aBaseH + off);
                ldm_x4(afl[mt], aBaseL + off);
            }
            unsigned bfh[4][4], bfl[4][4];
#pragma unroll
            for (int nt = 0; nt < 4; nt++) {
                unsigned off = ((kk + (lane & 15)) * BSTR + wn + nt * 16 + (lane >> 4) * 8) * 2;
                ldm_x4_t(bfh[nt], bBaseH + off);
                ldm_x4_t(bfl[nt], bBaseL + off);
            }
#pragma unroll
            for (int mt = 0; mt < 2; mt++)
#pragma unroll
                for (int nt = 0; nt < 4; nt++) {
                    mma16816(acc[mt][2 * nt],     afh[mt], &bfh[nt][0]);
                    mma16816(acc[mt][2 * nt + 1], afh[mt], &bfh[nt][2]);
                    mma16816(acc[mt][2 * nt],     afh[mt], &bfl[nt][0]);
                    mma16816(acc[mt][2 * nt + 1], afh[mt], &bfl[nt][2]);
                    mma16816(acc[mt][2 * nt],     afl[mt], &bfh[nt][0]);
                    mma16816(acc[mt][2 * nt + 1], afl[mt], &bfh[nt][2]);
                }
        }
        __syncthreads();
    }

    // epilogue: + bias, write fp32 Q
#pragma unroll
    for (int mt = 0; mt < 2; mt++) {
        int row0 = bm + wm + mt * 16 + (lane >> 2);
#pragma unroll
        for (int n8 = 0; n8 < 8; n8++) {
            int col = bn + wn + n8 * 8 + (lane & 3) * 2;
            float b0 = bias[col], b1 = bias[col + 1];
            float2 v0, v1;
            v0.x = acc[mt][n8][0] + b0; v0.y = acc[mt][n8][1] + b1;
            v1.x = acc[mt][n8][2] + b0; v1.y = acc[mt][n8][3] + b1;
            *(float2*)(g_Q + (size_t)row0 * HIDs + col)       = v0;
            *(float2*)(g_Q + (size_t)(row0 + 8) * HIDs + col) = v1;
        }
    }
}

// ---------------------------------------------------------------------------
// K2: pair scores. One warp per (b,i): float4 coalesced loads, 6 passes of
// 128 dims; each pass covers heads 2p (lanes 0-15) and 2p+1 (lanes 16-31).
// ---------------------------------------------------------------------------
__global__ __launch_bounds__(256) void k_dots() {
    int p = blockIdx.x * 8 + (threadIdx.x >> 5);   // pair index, 0..8175
    int lane = threadIdx.x & 31;
    int b = p / (Msz - 1);
    int i = p - b * (Msz - 1);
    const float* qa = g_Q + ((size_t)b * Msz + i) * HIDs;
    const float* qb = qa + HIDs;
#pragma unroll
    for (int pass = 0; pass < 6; pass++) {
        int d = pass * 128 + lane * 4;
        float4 a4 = *(const float4*)(qa + d);
        float4 b4 = *(const float4*)(qb + d);
        float s = a4.x * b4.x + a4.y * b4.y + a4.z * b4.z + a4.w * b4.w;
#pragma unroll
        for (int off = 8; off; off >>= 1) s += __shfl_xor_sync(0xffffffffu, s, off);
        if ((lane & 15) == 0) {
            int h = pass * 2 + (lane >> 4);
            g_s[(b * NH + h) * Msz + i] = s * (1.0f / 64.0f);
        }
    }
}

// ---------------------------------------------------------------------------
// K3: softmax band + prefix sums
// ---------------------------------------------------------------------------
__global__ void k_band(const float* __restrict__ prior, const int* __restrict__ mask) {
    int bh = blockIdx.x;
    int b  = bh / NH;
    int i  = threadIdx.x;
    __shared__ float  sh_s[Msz];
    __shared__ float  sh_an[Msz];
    __shared__ float  sh_ap[Msz];
    __shared__ double sh_sc[Msz];

    sh_s[i] = (i < Msz - 1) ? g_s[bh * Msz + i] : 0.f;
    __syncthreads();

    bool hp = (i > 0)       && (mask[b * Msz + i - 1] > 0);
    bool hn = (i < Msz - 1) && (mask[b * Msz + i + 1] > 0);
    float an = 0.f, ap = 0.f;
    if (hn && hp) {
        float sn = sh_s[i], sp = sh_s[i - 1];
        float m  = fmaxf(sn, sp);
        float en = expf(sn - m), ep = expf(sp - m);
        float z  = en + ep;
        an = en / z;
        ap = ep / z;
    } else if (hn) { an = 1.f; }
    else if (hp)   { ap = 1.f; }
    sh_an[i] = an;
    sh_ap[i] = ap;
    __syncthreads();

    float l = 0.f;
    if (i < Msz - 1) {
        float v    = sqrtf(sh_an[i] * sh_ap[i + 1] + 1e-4f);
        float prs  = prior[((size_t)b * Msz + i) * Msz + (i + 1)];
        float prb  = prior[((size_t)b * Msz + i + 1) * Msz + i];
        float nsup = prs + (1.f - prs) * v;
        float nsub = prb + (1.f - prb) * v;
        g_nasup[bh * Msz + i] = nsup;
        g_nasub[bh * Msz + i] = nsub;
        l = logf(nsup + 1e-9f);
    }
    sh_sc[i] = (double)l;
    __syncthreads();
    for (int off = 1; off < Msz; off <<= 1) {
        double t = (i >= off) ? sh_sc[i - off] : 0.0;
        __syncthreads();
        sh_sc[i] += t;
        __syncthreads();
    }
    g_S[bh * Msz + i] = (i == 0) ? 0.f : (float)sh_sc[i - 1];
}

// ---------------------------------------------------------------------------
// K4: output writer. Grid (Msz/4, Bsz). Thread owns 2 separated 4-col chunks
// (c and c+256) so each st.v4 is 32 consecutive lanes -> 4 L1 wavefronts.
// ---------------------------------------------------------------------------
__global__ __launch_bounds__(256) void k_out(const float* __restrict__ prior,
                                             float* __restrict__ gout,
                                             float* __restrict__ nbout) {
    int b = blockIdx.y;
    __shared__ float shS[NH][Msz];  // 24 KB
    const float* Sbase = g_S + (size_t)b * NH * Msz;
    for (int idx = threadIdx.x * 4; idx < NH * Msz; idx += 256 * 4)
        *(float4*)(&shS[0][0] + idx) = *(const float4*)(Sbase + idx);
    __syncthreads();

    int r  = threadIdx.x >> 6;
    int i  = blockIdx.x * 4 + r;
    int c0 = (threadIdx.x & 63) * 4;       // chunk A
    int c1 = c0 + 256;                     // chunk B
    const float SQEPS = 0.01f;

    const float* prow = prior + ((size_t)b * Msz + i) * Msz;
    float4 p0 = *(const float4*)(prow + c0);
    float4 p1 = *(const float4*)(prow + c1);
    float nbg0[4], nbg1[4];
    nbg0[0] = p0.x + (1.f - p0.x) * SQEPS; nbg0[1] = p0.y + (1.f - p0.y) * SQEPS;
    nbg0[2] = p0.z + (1.f - p0.z) * SQEPS; nbg0[3] = p0.w + (1.f - p0.w) * SQEPS;
    nbg1[0] = p1.x + (1.f - p1.x) * SQEPS; nbg1[1] = p1.y + (1.f - p1.y) * SQEPS;
    nbg1[2] = p1.z + (1.f - p1.z) * SQEPS; nbg1[3] = p1.w + (1.f - p1.w) * SQEPS;

    size_t rowbase = ((size_t)(b * NH) * Msz + i) * Msz;

    for (int h = 0; h < NH; h++) {
        int bh   = b * NH + h;
        float Si = shS[h][i];
        size_t off = rowbase + (size_t)h * Msz * Msz;

#pragma unroll
        for (int ch = 0; ch < 2; ch++) {
            int c = ch ? c1 : c0;
            const float* nbg = ch ? nbg1 : nbg0;
            float4 s4 = *(float4*)&shS[h][c];
            float sv[4]; sv[0] = s4.x; sv[1] = s4.y; sv[2] = s4.z; sv[3] = s4.w;
            float go[4], no[4];
#pragma unroll
            for (int j = 0; j < 4; j++) {
                int k    = c + j;
                float dS = (k > i) ? (sv[j] - Si) : (Si - sv[j]);
                float e  = (dS > -18.f) ? __expf(dS) : 0.f;
                go[j] = e + 1e-4f;
                no[j] = nbg[j];
            }
            if (i >= c && i < c + 4)                       go[i - c] = nbg[i - c];
            if (i + 1 >= c && i + 1 < c + 4)               no[i + 1 - c] = g_nasup[bh * Msz + i];
            if (i >= 1 && i - 1 >= c && i - 1 < c + 4)     no[i - 1 - c] = g_nasub[bh * Msz + (i - 1)];

            stcs4(gout + off + c,  go[0], go[1], go[2], go[3]);
            stcs4(nbout + off + c, no[0], no[1], no[2], no[3]);
        }
    }
}

extern "C" void kernel_launch(void* const* d_in, const int* in_sizes, int n_in,
                              void* d_out, int out_size) {
    const float* X     = (const float*)d_in[0];  // (16,512,768)
    const float* prior = (const float*)d_in[1];  // (16,1,512,512)
    const float* Wq    = (const float*)d_in[2];  // (768,768)
    const float* bq    = (const float*)d_in[3];  // (768,)
    const int*   mask  = (const int*)d_in[4];    // (16,512)
    float* out   = (float*)d_out;
    float* gout  = out;
    float* nbout = out + (size_t)BHsz * Msz * Msz;

    __nv_bfloat16 *dAh, *dAl, *dWh, *dWl;
    cudaGetSymbolAddress((void**)&dAh, g_Ah);
    cudaGetSymbolAddress((void**)&dAl, g_Al);
    cudaGetSymbolAddress((void**)&dWh, g_Wh);
    cudaGetSymbolAddress((void**)&dWl, g_Wl);

    cudaFuncSetAttribute(k_gemm_mma, cudaFuncAttributeMaxDynamicSharedMemorySize,
                         SMEM_BYTES);

    int nX = Bsz * Msz * HIDs;
    int nW = HIDs * HIDs;
    k_cvt<<<(nX / 4 + 255) / 256, 256>>>(X, dAh, dAl, nX);
    k_cvt<<<(nW / 4 + 255) / 256, 256>>>(Wq, dWh, dWl, nW);
    k_gemm_mma<<<dim3(HIDs / BN, (Bsz * Msz) / BM), 256, SMEM_BYTES>>>(bq);
    k_dots<<<(Bsz * (Msz - 1)) / 8, 256>>>();
    k_band<<<BHsz, Msz>>>(prior, mask);
    k_out<<<dim3(Msz / 4, Bsz), 256>>>(prior, gout, nbout);
}